// round 1
// baseline (speedup 1.0000x reference)
#include <cuda_runtime.h>
#include <cuda_bf16.h>
#include <cstdint>

// Problem constants (fixed shapes for this problem)
#define N_NODES 100000
#define DIM     128
#define ALPHA_C 0.1f
#define BETA_C  0.4054651081081644f   // ln(1.5)

// Scratch (device globals: allocation is forbidden)
__device__ __align__(256) float g_side[(size_t)N_NODES * DIM];
__device__ __align__(256) float g_M1[DIM * DIM];
__device__ __align__(256) float g_M2[DIM * DIM];

// ---------------------------------------------------------------------------
// Kernel A: M1 = im @ w1, M2 = im @ w2,  im = (1-beta) + beta*weight
// grid = 128 blocks (one output row each), 128 threads
// ---------------------------------------------------------------------------
__global__ void compute_M_kernel(const float* __restrict__ weight,
                                 const float* __restrict__ w1,
                                 const float* __restrict__ w2) {
    __shared__ float sIm[DIM];
    const int i = blockIdx.x;
    const int j = threadIdx.x;
    sIm[j] = (1.0f - BETA_C) + BETA_C * weight[i * DIM + j];
    __syncthreads();
    float a1 = 0.0f, a2 = 0.0f;
#pragma unroll 8
    for (int k = 0; k < DIM; k++) {
        const float im = sIm[k];
        a1 = fmaf(im, __ldg(w1 + k * DIM + j), a1);
        a2 = fmaf(im, __ldg(w2 + k * DIM + j), a2);
    }
    g_M1[i * DIM + j] = a1;
    g_M2[i * DIM + j] = a2;
}

// ---------------------------------------------------------------------------
// Kernel B: zero the scatter buffer
// ---------------------------------------------------------------------------
__global__ void zero_side_kernel() {
    const int idx = blockIdx.x * blockDim.x + threadIdx.x;
    const int total = N_NODES * DIM / 4;
    if (idx < total) {
        reinterpret_cast<float4*>(g_side)[idx] = make_float4(0.f, 0.f, 0.f, 0.f);
    }
}

// ---------------------------------------------------------------------------
// Kernel C: SpMM scatter  side[row[e]] += vals[e] * ego[col[e]]
// one warp per edge; float4 gather + red.global.add.v4.f32 scatter
// ---------------------------------------------------------------------------
__global__ void spmm_kernel(const float* __restrict__ ego,
                            const float* __restrict__ vals,
                            const int*   __restrict__ row,
                            const int*   __restrict__ col,
                            int E) {
    const int gw   = (blockIdx.x * blockDim.x + threadIdx.x) >> 5;
    const int lane = threadIdx.x & 31;
    if (gw >= E) return;
    const int   r = __ldg(row + gw);
    const int   c = __ldg(col + gw);
    const float v = __ldg(vals + gw);

    const float4 e = __ldg(reinterpret_cast<const float4*>(ego + (size_t)c * DIM) + lane);
    float4 p;
    p.x = v * e.x; p.y = v * e.y; p.z = v * e.z; p.w = v * e.w;

    float* dst = g_side + (size_t)r * DIM + lane * 4;
    asm volatile("red.global.add.v4.f32 [%0], {%1, %2, %3, %4};"
                 :: "l"(dst), "f"(p.x), "f"(p.y), "f"(p.z), "f"(p.w)
                 : "memory");
}

// ---------------------------------------------------------------------------
// Kernel D: fused residual + bi-interaction + GEMM + leakyrelu + add
//   X1 = (1-a)*(ego+side) + a*h0 ;  X2 = (1-a)*(ego*side) + a*h0
//   out = lrelu(X1@M1 + b1) + lrelu(X2@M2 + b2)
// Tile: 64 rows/block, 256 threads, per-thread 8 rows x 4 cols x 2 accums.
// smem: M1(64K) + M2(64K) + X1(32K) + X2(32K) = 192KB dynamic
// ---------------------------------------------------------------------------
#define F_ROWS    64
#define F_THREADS 256

__device__ __forceinline__ float lrelu(float x) {
    return fmaxf(x, 0.01f * x);
}

extern __shared__ float f_smem[];

__global__ __launch_bounds__(F_THREADS, 1)
void fused_kernel(const float* __restrict__ ego,
                  const float* __restrict__ h0,
                  const float* __restrict__ b1,
                  const float* __restrict__ b2,
                  float* __restrict__ out) {
    float* sM1 = f_smem;                 // [128][128]
    float* sM2 = sM1 + DIM * DIM;        // [128][128]
    float* sX1 = sM2 + DIM * DIM;        // [64][128]
    float* sX2 = sX1 + F_ROWS * DIM;     // [64][128]

    const int tid  = threadIdx.x;
    const int row0 = blockIdx.x * F_ROWS;

    // Load M1/M2 into shared (float4, 2 x 4096 float4s, 16 each/thread)
    {
        const float4* gm1 = reinterpret_cast<const float4*>(g_M1);
        const float4* gm2 = reinterpret_cast<const float4*>(g_M2);
        float4* m1 = reinterpret_cast<float4*>(sM1);
        float4* m2 = reinterpret_cast<float4*>(sM2);
#pragma unroll
        for (int i = tid; i < DIM * DIM / 4; i += F_THREADS) {
            m1[i] = gm1[i];
            m2[i] = gm2[i];
        }
    }

    // Build X1/X2 tiles in shared
    {
        float4* x1s = reinterpret_cast<float4*>(sX1);
        float4* x2s = reinterpret_cast<float4*>(sX2);
#pragma unroll
        for (int i = tid; i < F_ROWS * DIM / 4; i += F_THREADS) {
            const int r  = i >> 5;       // i / 32
            const int cc = i & 31;
            const int grow = row0 + r;
            float4 x1 = make_float4(0.f, 0.f, 0.f, 0.f);
            float4 x2 = x1;
            if (grow < N_NODES) {
                const float4 e = __ldg(reinterpret_cast<const float4*>(ego + (size_t)grow * DIM) + cc);
                const float4 s = *(reinterpret_cast<const float4*>(g_side + (size_t)grow * DIM) + cc);
                const float4 h = __ldg(reinterpret_cast<const float4*>(h0 + (size_t)grow * DIM) + cc);
                const float oa = 1.0f - ALPHA_C;
                x1.x = oa * (e.x + s.x) + ALPHA_C * h.x;
                x1.y = oa * (e.y + s.y) + ALPHA_C * h.y;
                x1.z = oa * (e.z + s.z) + ALPHA_C * h.z;
                x1.w = oa * (e.w + s.w) + ALPHA_C * h.w;
                x2.x = oa * (e.x * s.x) + ALPHA_C * h.x;
                x2.y = oa * (e.y * s.y) + ALPHA_C * h.y;
                x2.z = oa * (e.z * s.z) + ALPHA_C * h.z;
                x2.w = oa * (e.w * s.w) + ALPHA_C * h.w;
            }
            x1s[i] = x1;
            x2s[i] = x2;
        }
    }
    __syncthreads();

    const int cg = tid & 31;   // column group: cols [cg*4, cg*4+4)
    const int rg = tid >> 5;   // row group:    rows [rg*8, rg*8+8)
    const int r0 = rg * 8;

    float4 acc1[8], acc2[8];
#pragma unroll
    for (int r = 0; r < 8; r++) {
        acc1[r] = make_float4(0.f, 0.f, 0.f, 0.f);
        acc2[r] = acc1[r];
    }

    // K loop, 4 k-steps at a time
    for (int k4 = 0; k4 < DIM / 4; k4++) {
        float4 m1v[4], m2v[4];
#pragma unroll
        for (int kk = 0; kk < 4; kk++) {
            const int k = k4 * 4 + kk;
            m1v[kk] = reinterpret_cast<const float4*>(sM1 + k * DIM)[cg];
            m2v[kk] = reinterpret_cast<const float4*>(sM2 + k * DIM)[cg];
        }
#pragma unroll
        for (int r = 0; r < 8; r++) {
            const float4 xa = reinterpret_cast<const float4*>(sX1 + (r0 + r) * DIM)[k4];
            const float4 xb = reinterpret_cast<const float4*>(sX2 + (r0 + r) * DIM)[k4];
            const float xs1[4] = {xa.x, xa.y, xa.z, xa.w};
            const float xs2[4] = {xb.x, xb.y, xb.z, xb.w};
#pragma unroll
            for (int kk = 0; kk < 4; kk++) {
                acc1[r].x = fmaf(xs1[kk], m1v[kk].x, acc1[r].x);
                acc1[r].y = fmaf(xs1[kk], m1v[kk].y, acc1[r].y);
                acc1[r].z = fmaf(xs1[kk], m1v[kk].z, acc1[r].z);
                acc1[r].w = fmaf(xs1[kk], m1v[kk].w, acc1[r].w);
                acc2[r].x = fmaf(xs2[kk], m2v[kk].x, acc2[r].x);
                acc2[r].y = fmaf(xs2[kk], m2v[kk].y, acc2[r].y);
                acc2[r].z = fmaf(xs2[kk], m2v[kk].z, acc2[r].z);
                acc2[r].w = fmaf(xs2[kk], m2v[kk].w, acc2[r].w);
            }
        }
    }

    // Epilogue: bias + leaky relu + add branches, store float4 per row
    const float4 bb1 = __ldg(reinterpret_cast<const float4*>(b1) + cg);
    const float4 bb2 = __ldg(reinterpret_cast<const float4*>(b2) + cg);
#pragma unroll
    for (int r = 0; r < 8; r++) {
        const int grow = row0 + r0 + r;
        if (grow < N_NODES) {
            float4 o;
            o.x = lrelu(acc1[r].x + bb1.x) + lrelu(acc2[r].x + bb2.x);
            o.y = lrelu(acc1[r].y + bb1.y) + lrelu(acc2[r].y + bb2.y);
            o.z = lrelu(acc1[r].z + bb1.z) + lrelu(acc2[r].z + bb2.z);
            o.w = lrelu(acc1[r].w + bb1.w) + lrelu(acc2[r].w + bb2.w);
            reinterpret_cast<float4*>(out + (size_t)grow * DIM)[cg] = o;
        }
    }
}

// ---------------------------------------------------------------------------
// Launch
// Inputs (metadata order): 0=ego(N*D) 1=h0(N*D) 2=vals(E) 3=weight(D*D)
//                          4=w1 5=b1 6=w2 7=b2 8=row(E,int) 9=col(E,int)
// ---------------------------------------------------------------------------
extern "C" void kernel_launch(void* const* d_in, const int* in_sizes, int n_in,
                              void* d_out, int out_size) {
    const float* ego    = (const float*)d_in[0];
    const float* h0     = (const float*)d_in[1];
    const float* vals   = (const float*)d_in[2];
    const float* weight = (const float*)d_in[3];
    const float* w1     = (const float*)d_in[4];
    const float* b1     = (const float*)d_in[5];
    const float* w2     = (const float*)d_in[6];
    const float* b2     = (const float*)d_in[7];
    const int*   row    = (const int*)d_in[8];
    const int*   col    = (const int*)d_in[9];
    float* out = (float*)d_out;

    const int E = in_sizes[2];

    // B: zero scatter buffer
    {
        const int total = N_NODES * DIM / 4;
        zero_side_kernel<<<(total + 255) / 256, 256>>>();
    }
    // A: fold weight matrices
    compute_M_kernel<<<DIM, DIM>>>(weight, w1, w2);

    // C: SpMM scatter (1 warp / edge)
    {
        const int warps_per_block = 8;
        const int blocks = (E + warps_per_block - 1) / warps_per_block;
        spmm_kernel<<<blocks, warps_per_block * 32>>>(ego, vals, row, col, E);
    }

    // D: fused dense
    {
        const int smem_bytes = (2 * DIM * DIM + 2 * F_ROWS * DIM) * (int)sizeof(float); // 192KB
        cudaFuncSetAttribute(fused_kernel, cudaFuncAttributeMaxDynamicSharedMemorySize, smem_bytes);
        const int blocks = (N_NODES + F_ROWS - 1) / F_ROWS;
        fused_kernel<<<blocks, F_THREADS, smem_bytes>>>(ego, h0, b1, b2, out);
    }
}

// round 3
// speedup vs baseline: 1.4586x; 1.4586x over previous
#include <cuda_runtime.h>
#include <cuda_bf16.h>
#include <cstdint>

#define N_NODES 100000
#define DIM     128
#define ALPHA_C 0.1f
#define BETA_C  0.4054651081081644f   // ln(1.5)
#define EMAX    3200000
#define SCAN_B  1024
#define NB_SCAN ((N_NODES + SCAN_B - 1) / SCAN_B)   // 98

// Scratch (device globals: allocation is forbidden)
__device__ __align__(256) float g_side[(size_t)N_NODES * DIM];
__device__ __align__(256) float g_M1[DIM * DIM];
__device__ __align__(256) float g_M2[DIM * DIM];
__device__ __align__(256) int   g_cnt[N_NODES];
__device__ __align__(256) int   g_scan[N_NODES];
__device__ __align__(256) int   g_start[N_NODES];
__device__ __align__(256) int   g_cursor[N_NODES];
__device__ __align__(256) int   g_bsum[SCAN_B];
__device__ __align__(256) int   g_boff[SCAN_B];
__device__ __align__(256) int   g_ecol[EMAX];
__device__ __align__(256) float g_eval[EMAX];

// ---------------------------------------------------------------------------
// M1 = im @ w1, M2 = im @ w2,  im = (1-beta)*I... no: (1-beta) + beta*weight (dense)
// ---------------------------------------------------------------------------
__global__ void compute_M_kernel(const float* __restrict__ weight,
                                 const float* __restrict__ w1,
                                 const float* __restrict__ w2) {
    __shared__ float sIm[DIM];
    const int i = blockIdx.x;
    const int j = threadIdx.x;
    sIm[j] = (1.0f - BETA_C) + BETA_C * weight[i * DIM + j];
    __syncthreads();
    float a1 = 0.0f, a2 = 0.0f;
#pragma unroll 8
    for (int k = 0; k < DIM; k++) {
        const float im = sIm[k];
        a1 = fmaf(im, __ldg(w1 + k * DIM + j), a1);
        a2 = fmaf(im, __ldg(w2 + k * DIM + j), a2);
    }
    g_M1[i * DIM + j] = a1;
    g_M2[i * DIM + j] = a2;
}

// ---------------------------------------------------------------------------
// CSR build: zero counts -> histogram -> scan (3 kernels) -> scatter
// ---------------------------------------------------------------------------
__global__ void zero_cnt_kernel() {
    const int i = blockIdx.x * blockDim.x + threadIdx.x;
    if (i < N_NODES) g_cnt[i] = 0;
}

__global__ void hist_kernel(const int* __restrict__ row, int E) {
    const int e = blockIdx.x * blockDim.x + threadIdx.x;
    if (e < E) atomicAdd(&g_cnt[__ldg(row + e)], 1);
}

__global__ void scan1_kernel() {
    __shared__ int s[SCAN_B];
    const int tid = threadIdx.x;
    const int i = blockIdx.x * SCAN_B + tid;
    int v = (i < N_NODES) ? g_cnt[i] : 0;
    s[tid] = v;
    __syncthreads();
#pragma unroll
    for (int off = 1; off < SCAN_B; off <<= 1) {
        int t = (tid >= off) ? s[tid - off] : 0;
        __syncthreads();
        s[tid] += t;
        __syncthreads();
    }
    if (i < N_NODES) g_scan[i] = s[tid];
    if (tid == SCAN_B - 1) g_bsum[blockIdx.x] = s[tid];
}

__global__ void scan2_kernel() {
    __shared__ int s[128];
    const int tid = threadIdx.x;   // 128 threads, NB_SCAN=98 <= 128
    int v = (tid < NB_SCAN) ? g_bsum[tid] : 0;
    s[tid] = v;
    __syncthreads();
#pragma unroll
    for (int off = 1; off < 128; off <<= 1) {
        int t = (tid >= off) ? s[tid - off] : 0;
        __syncthreads();
        s[tid] += t;
        __syncthreads();
    }
    if (tid < NB_SCAN) g_boff[tid] = s[tid] - v;   // exclusive
}

__global__ void scan3_kernel() {
    const int i = blockIdx.x * blockDim.x + threadIdx.x;
    if (i < N_NODES) {
        const int excl = g_scan[i] - g_cnt[i] + g_boff[i / SCAN_B];
        g_start[i]  = excl;
        g_cursor[i] = excl;
    }
}

__global__ void scatter_kernel(const int* __restrict__ row,
                               const int* __restrict__ col,
                               const float* __restrict__ vals, int E) {
    const int e = blockIdx.x * blockDim.x + threadIdx.x;
    if (e < E) {
        const int r = __ldg(row + e);
        const int pos = atomicAdd(&g_cursor[r], 1);
        g_ecol[pos] = __ldg(col + e);
        g_eval[pos] = __ldg(vals + e);
    }
}

// ---------------------------------------------------------------------------
// Gather SpMM: one warp per row. side[r] = sum_e val[e] * ego[col[e]]
// ---------------------------------------------------------------------------
__global__ __launch_bounds__(256)
void gather_spmm_kernel(const float* __restrict__ ego) {
    const int wid  = (blockIdx.x * blockDim.x + threadIdx.x) >> 5;
    const int lane = threadIdx.x & 31;
    if (wid >= N_NODES) return;

    const int start = g_start[wid];
    const int cnt   = g_cnt[wid];

    float4 acc = make_float4(0.f, 0.f, 0.f, 0.f);

    for (int j0 = 0; j0 < cnt; j0 += 32) {
        const int rem = min(32, cnt - j0);
        int   myc = 0;
        float myv = 0.f;
        if (lane < rem) {
            myc = __ldg(g_ecol + start + j0 + lane);
            myv = __ldg(g_eval + start + j0 + lane);
        }
        int kk = 0;
        // unrolled-by-4 body: independent gathers -> MLP 4 per warp
        for (; kk + 4 <= rem; kk += 4) {
            const int   c0 = __shfl_sync(0xffffffffu, myc, kk + 0);
            const int   c1 = __shfl_sync(0xffffffffu, myc, kk + 1);
            const int   c2 = __shfl_sync(0xffffffffu, myc, kk + 2);
            const int   c3 = __shfl_sync(0xffffffffu, myc, kk + 3);
            const float v0 = __shfl_sync(0xffffffffu, myv, kk + 0);
            const float v1 = __shfl_sync(0xffffffffu, myv, kk + 1);
            const float v2 = __shfl_sync(0xffffffffu, myv, kk + 2);
            const float v3 = __shfl_sync(0xffffffffu, myv, kk + 3);
            const float4 e0 = __ldg(reinterpret_cast<const float4*>(ego + (size_t)c0 * DIM) + lane);
            const float4 e1 = __ldg(reinterpret_cast<const float4*>(ego + (size_t)c1 * DIM) + lane);
            const float4 e2 = __ldg(reinterpret_cast<const float4*>(ego + (size_t)c2 * DIM) + lane);
            const float4 e3 = __ldg(reinterpret_cast<const float4*>(ego + (size_t)c3 * DIM) + lane);
            acc.x = fmaf(v0, e0.x, acc.x); acc.y = fmaf(v0, e0.y, acc.y);
            acc.z = fmaf(v0, e0.z, acc.z); acc.w = fmaf(v0, e0.w, acc.w);
            acc.x = fmaf(v1, e1.x, acc.x); acc.y = fmaf(v1, e1.y, acc.y);
            acc.z = fmaf(v1, e1.z, acc.z); acc.w = fmaf(v1, e1.w, acc.w);
            acc.x = fmaf(v2, e2.x, acc.x); acc.y = fmaf(v2, e2.y, acc.y);
            acc.z = fmaf(v2, e2.z, acc.z); acc.w = fmaf(v2, e2.w, acc.w);
            acc.x = fmaf(v3, e3.x, acc.x); acc.y = fmaf(v3, e3.y, acc.y);
            acc.z = fmaf(v3, e3.z, acc.z); acc.w = fmaf(v3, e3.w, acc.w);
        }
        for (; kk < rem; kk++) {
            const int   c = __shfl_sync(0xffffffffu, myc, kk);
            const float v = __shfl_sync(0xffffffffu, myv, kk);
            const float4 e = __ldg(reinterpret_cast<const float4*>(ego + (size_t)c * DIM) + lane);
            acc.x = fmaf(v, e.x, acc.x); acc.y = fmaf(v, e.y, acc.y);
            acc.z = fmaf(v, e.z, acc.z); acc.w = fmaf(v, e.w, acc.w);
        }
    }
    reinterpret_cast<float4*>(g_side + (size_t)wid * DIM)[lane] = acc;
}

// ---------------------------------------------------------------------------
// Fused residual + bi-interaction + GEMM + leakyrelu + add (unchanged)
// ---------------------------------------------------------------------------
#define F_ROWS    64
#define F_THREADS 256

__device__ __forceinline__ float lrelu(float x) {
    return fmaxf(x, 0.01f * x);
}

extern __shared__ float f_smem[];

__global__ __launch_bounds__(F_THREADS, 1)
void fused_kernel(const float* __restrict__ ego,
                  const float* __restrict__ h0,
                  const float* __restrict__ b1,
                  const float* __restrict__ b2,
                  float* __restrict__ out) {
    float* sM1 = f_smem;
    float* sM2 = sM1 + DIM * DIM;
    float* sX1 = sM2 + DIM * DIM;
    float* sX2 = sX1 + F_ROWS * DIM;

    const int tid  = threadIdx.x;
    const int row0 = blockIdx.x * F_ROWS;

    {
        const float4* gm1 = reinterpret_cast<const float4*>(g_M1);
        const float4* gm2 = reinterpret_cast<const float4*>(g_M2);
        float4* m1 = reinterpret_cast<float4*>(sM1);
        float4* m2 = reinterpret_cast<float4*>(sM2);
#pragma unroll
        for (int i = tid; i < DIM * DIM / 4; i += F_THREADS) {
            m1[i] = gm1[i];
            m2[i] = gm2[i];
        }
    }

    {
        float4* x1s = reinterpret_cast<float4*>(sX1);
        float4* x2s = reinterpret_cast<float4*>(sX2);
#pragma unroll
        for (int i = tid; i < F_ROWS * DIM / 4; i += F_THREADS) {
            const int r  = i >> 5;
            const int cc = i & 31;
            const int grow = row0 + r;
            float4 x1 = make_float4(0.f, 0.f, 0.f, 0.f);
            float4 x2 = x1;
            if (grow < N_NODES) {
                const float4 e = __ldg(reinterpret_cast<const float4*>(ego + (size_t)grow * DIM) + cc);
                const float4 s = *(reinterpret_cast<const float4*>(g_side + (size_t)grow * DIM) + cc);
                const float4 h = __ldg(reinterpret_cast<const float4*>(h0 + (size_t)grow * DIM) + cc);
                const float oa = 1.0f - ALPHA_C;
                x1.x = oa * (e.x + s.x) + ALPHA_C * h.x;
                x1.y = oa * (e.y + s.y) + ALPHA_C * h.y;
                x1.z = oa * (e.z + s.z) + ALPHA_C * h.z;
                x1.w = oa * (e.w + s.w) + ALPHA_C * h.w;
                x2.x = oa * (e.x * s.x) + ALPHA_C * h.x;
                x2.y = oa * (e.y * s.y) + ALPHA_C * h.y;
                x2.z = oa * (e.z * s.z) + ALPHA_C * h.z;
                x2.w = oa * (e.w * s.w) + ALPHA_C * h.w;
            }
            x1s[i] = x1;
            x2s[i] = x2;
        }
    }
    __syncthreads();

    const int cg = tid & 31;
    const int rg = tid >> 5;
    const int r0 = rg * 8;

    float4 acc1[8], acc2[8];
#pragma unroll
    for (int r = 0; r < 8; r++) {
        acc1[r] = make_float4(0.f, 0.f, 0.f, 0.f);
        acc2[r] = acc1[r];
    }

    for (int k4 = 0; k4 < DIM / 4; k4++) {
        float4 m1v[4], m2v[4];
#pragma unroll
        for (int kk = 0; kk < 4; kk++) {
            const int k = k4 * 4 + kk;
            m1v[kk] = reinterpret_cast<const float4*>(sM1 + k * DIM)[cg];
            m2v[kk] = reinterpret_cast<const float4*>(sM2 + k * DIM)[cg];
        }
#pragma unroll
        for (int r = 0; r < 8; r++) {
            const float4 xa = reinterpret_cast<const float4*>(sX1 + (r0 + r) * DIM)[k4];
            const float4 xb = reinterpret_cast<const float4*>(sX2 + (r0 + r) * DIM)[k4];
            const float xs1[4] = {xa.x, xa.y, xa.z, xa.w};
            const float xs2[4] = {xb.x, xb.y, xb.z, xb.w};
#pragma unroll
            for (int kk = 0; kk < 4; kk++) {
                acc1[r].x = fmaf(xs1[kk], m1v[kk].x, acc1[r].x);
                acc1[r].y = fmaf(xs1[kk], m1v[kk].y, acc1[r].y);
                acc1[r].z = fmaf(xs1[kk], m1v[kk].z, acc1[r].z);
                acc1[r].w = fmaf(xs1[kk], m1v[kk].w, acc1[r].w);
                acc2[r].x = fmaf(xs2[kk], m2v[kk].x, acc2[r].x);
                acc2[r].y = fmaf(xs2[kk], m2v[kk].y, acc2[r].y);
                acc2[r].z = fmaf(xs2[kk], m2v[kk].z, acc2[r].z);
                acc2[r].w = fmaf(xs2[kk], m2v[kk].w, acc2[r].w);
            }
        }
    }

    const float4 bb1 = __ldg(reinterpret_cast<const float4*>(b1) + cg);
    const float4 bb2 = __ldg(reinterpret_cast<const float4*>(b2) + cg);
#pragma unroll
    for (int r = 0; r < 8; r++) {
        const int grow = row0 + r0 + r;
        if (grow < N_NODES) {
            float4 o;
            o.x = lrelu(acc1[r].x + bb1.x) + lrelu(acc2[r].x + bb2.x);
            o.y = lrelu(acc1[r].y + bb1.y) + lrelu(acc2[r].y + bb2.y);
            o.z = lrelu(acc1[r].z + bb1.z) + lrelu(acc2[r].z + bb2.z);
            o.w = lrelu(acc1[r].w + bb1.w) + lrelu(acc2[r].w + bb2.w);
            reinterpret_cast<float4*>(out + (size_t)grow * DIM)[cg] = o;
        }
    }
}

// ---------------------------------------------------------------------------
// Launch
// Inputs: 0=ego 1=h0 2=vals 3=weight 4=w1 5=b1 6=w2 7=b2 8=row 9=col
// ---------------------------------------------------------------------------
extern "C" void kernel_launch(void* const* d_in, const int* in_sizes, int n_in,
                              void* d_out, int out_size) {
    const float* ego    = (const float*)d_in[0];
    const float* h0     = (const float*)d_in[1];
    const float* vals   = (const float*)d_in[2];
    const float* weight = (const float*)d_in[3];
    const float* w1     = (const float*)d_in[4];
    const float* b1     = (const float*)d_in[5];
    const float* w2     = (const float*)d_in[6];
    const float* b2     = (const float*)d_in[7];
    const int*   row    = (const int*)d_in[8];
    const int*   col    = (const int*)d_in[9];
    float* out = (float*)d_out;

    const int E = in_sizes[2];

    // Fold weight matrices (independent of everything else)
    compute_M_kernel<<<DIM, DIM>>>(weight, w1, w2);

    // CSR build
    zero_cnt_kernel<<<(N_NODES + 255) / 256, 256>>>();
    hist_kernel<<<(E + 255) / 256, 256>>>(row, E);
    scan1_kernel<<<NB_SCAN, SCAN_B>>>();
    scan2_kernel<<<1, 128>>>();
    scan3_kernel<<<(N_NODES + 255) / 256, 256>>>();
    scatter_kernel<<<(E + 255) / 256, 256>>>(row, col, vals, E);

    // Gather SpMM (one warp per row)
    {
        const int warps_per_block = 8;
        const int blocks = (N_NODES + warps_per_block - 1) / warps_per_block;
        gather_spmm_kernel<<<blocks, warps_per_block * 32>>>(ego);
    }

    // Fused dense
    {
        const int smem_bytes = (2 * DIM * DIM + 2 * F_ROWS * DIM) * (int)sizeof(float);
        cudaFuncSetAttribute(fused_kernel, cudaFuncAttributeMaxDynamicSharedMemorySize, smem_bytes);
        const int blocks = (N_NODES + F_ROWS - 1) / F_ROWS;
        fused_kernel<<<blocks, F_THREADS, smem_bytes>>>(ego, h0, b1, b2, out);
    }
}

// round 6
// speedup vs baseline: 1.7272x; 1.1841x over previous
#include <cuda_runtime.h>
#include <cuda_bf16.h>
#include <cstdint>

#define N_NODES 100000
#define DIM     128
#define ALPHA_C 0.1f
#define BETA_C  0.4054651081081644f   // ln(1.5)
#define EMAX    3200000
#define SCAN_B  1024
#define NB_SCAN ((N_NODES + SCAN_B - 1) / SCAN_B)   // 98

// Padded bf16 tile layout: row stride 136 elements (272 bytes, 16B-aligned,
// conflict-free for ldmatrix: 272 mod 128 = 16 -> 8 rows hit distinct 16B banks)
#define TSTRIDE 136
#define TILE_ELEMS (DIM * TSTRIDE)          // 17408 bf16 per image
#define TILE_BYTES (TILE_ELEMS * 2)         // 34816 B

// ---------------------------------------------------------------------------
// Device scratch (allocation is forbidden)
// ---------------------------------------------------------------------------
__device__ __align__(256) float g_side[(size_t)N_NODES * DIM];
__device__ __align__(256) int   g_cnt[N_NODES];
__device__ __align__(256) int   g_scan[N_NODES];
__device__ __align__(256) int   g_start[N_NODES];
__device__ __align__(256) int   g_cursor[N_NODES];
__device__ __align__(256) int   g_bsum[SCAN_B];
__device__ __align__(256) int   g_boff[SCAN_B];
__device__ __align__(256) int   g_ecol[EMAX];
__device__ __align__(256) float g_eval[EMAX];
// Packed B images: [0]=B1h [1]=B1l [2]=B2h [3]=B2l, each [n][k] stride TSTRIDE
__device__ __align__(256) __nv_bfloat16 g_Bpack[4 * TILE_ELEMS];

// ---------------------------------------------------------------------------
// PTX helpers: ldmatrix + bf16 mma (target-portable, works on compute_103)
// ---------------------------------------------------------------------------
__device__ __forceinline__ uint32_t smem_u32(const void* p) {
    uint32_t a;
    asm("{ .reg .u64 t; cvta.to.shared.u64 t, %1; cvt.u32.u64 %0, t; }" : "=r"(a) : "l"(p));
    return a;
}
__device__ __forceinline__ void ldmat_x4(uint32_t* r, uint32_t addr) {
    asm volatile("ldmatrix.sync.aligned.m8n8.x4.shared.b16 {%0,%1,%2,%3}, [%4];"
                 : "=r"(r[0]), "=r"(r[1]), "=r"(r[2]), "=r"(r[3]) : "r"(addr));
}
__device__ __forceinline__ void mma_bf16(float* d, const uint32_t* a, const uint32_t* b) {
    asm volatile(
        "mma.sync.aligned.m16n8k16.row.col.f32.bf16.bf16.f32 "
        "{%0,%1,%2,%3},{%4,%5,%6,%7},{%8,%9},{%0,%1,%2,%3};"
        : "+f"(d[0]), "+f"(d[1]), "+f"(d[2]), "+f"(d[3])
        : "r"(a[0]), "r"(a[1]), "r"(a[2]), "r"(a[3]), "r"(b[0]), "r"(b[1]));
}

__device__ __forceinline__ float lrelu(float x) { return fmaxf(x, 0.01f * x); }

// ---------------------------------------------------------------------------
// compute_M: M1 = im@w1, M2 = im@w2 (im = (1-beta)+beta*weight); store
// transposed hi/lo bf16 into padded [n][k] images.
// grid=(128) -> k index, block=(128) -> n index
// ---------------------------------------------------------------------------
__global__ void compute_M_kernel(const float* __restrict__ weight,
                                 const float* __restrict__ w1,
                                 const float* __restrict__ w2) {
    __shared__ float sIm[DIM];
    const int i = blockIdx.x;   // k
    const int j = threadIdx.x;  // n
    sIm[j] = (1.0f - BETA_C) + BETA_C * weight[i * DIM + j];
    __syncthreads();
    float a1 = 0.0f, a2 = 0.0f;
#pragma unroll 8
    for (int k = 0; k < DIM; k++) {
        const float im = sIm[k];
        a1 = fmaf(im, __ldg(w1 + k * DIM + j), a1);
        a2 = fmaf(im, __ldg(w2 + k * DIM + j), a2);
    }
    const __nv_bfloat16 h1 = __float2bfloat16(a1);
    const __nv_bfloat16 l1 = __float2bfloat16(a1 - __bfloat162float(h1));
    const __nv_bfloat16 h2 = __float2bfloat16(a2);
    const __nv_bfloat16 l2 = __float2bfloat16(a2 - __bfloat162float(h2));
    const int base = j * TSTRIDE + i;    // [n][k]
    g_Bpack[0 * TILE_ELEMS + base] = h1;
    g_Bpack[1 * TILE_ELEMS + base] = l1;
    g_Bpack[2 * TILE_ELEMS + base] = h2;
    g_Bpack[3 * TILE_ELEMS + base] = l2;
}

// ---------------------------------------------------------------------------
// CSR build: zero counts -> histogram -> scan (3 kernels) -> scatter
// ---------------------------------------------------------------------------
__global__ void zero_cnt_kernel() {
    const int i = blockIdx.x * blockDim.x + threadIdx.x;
    if (i < N_NODES) g_cnt[i] = 0;
}
__global__ void hist_kernel(const int* __restrict__ row, int E) {
    const int e = blockIdx.x * blockDim.x + threadIdx.x;
    if (e < E) atomicAdd(&g_cnt[__ldg(row + e)], 1);
}
__global__ void scan1_kernel() {
    __shared__ int s[SCAN_B];
    const int tid = threadIdx.x;
    const int i = blockIdx.x * SCAN_B + tid;
    int v = (i < N_NODES) ? g_cnt[i] : 0;
    s[tid] = v;
    __syncthreads();
#pragma unroll
    for (int off = 1; off < SCAN_B; off <<= 1) {
        int t = (tid >= off) ? s[tid - off] : 0;
        __syncthreads();
        s[tid] += t;
        __syncthreads();
    }
    if (i < N_NODES) g_scan[i] = s[tid];
    if (tid == SCAN_B - 1) g_bsum[blockIdx.x] = s[tid];
}
__global__ void scan2_kernel() {
    __shared__ int s[128];
    const int tid = threadIdx.x;
    int v = (tid < NB_SCAN) ? g_bsum[tid] : 0;
    s[tid] = v;
    __syncthreads();
#pragma unroll
    for (int off = 1; off < 128; off <<= 1) {
        int t = (tid >= off) ? s[tid - off] : 0;
        __syncthreads();
        s[tid] += t;
        __syncthreads();
    }
    if (tid < NB_SCAN) g_boff[tid] = s[tid] - v;
}
__global__ void scan3_kernel() {
    const int i = blockIdx.x * blockDim.x + threadIdx.x;
    if (i < N_NODES) {
        const int excl = g_scan[i] - g_cnt[i] + g_boff[i / SCAN_B];
        g_start[i]  = excl;
        g_cursor[i] = excl;
    }
}
__global__ void scatter_kernel(const int* __restrict__ row,
                               const int* __restrict__ col,
                               const float* __restrict__ vals, int E) {
    const int e = blockIdx.x * blockDim.x + threadIdx.x;
    if (e < E) {
        const int r = __ldg(row + e);
        const int pos = atomicAdd(&g_cursor[r], 1);
        g_ecol[pos] = __ldg(col + e);
        g_eval[pos] = __ldg(vals + e);
    }
}

// ---------------------------------------------------------------------------
// Gather SpMM: one warp per row. side[r] = sum_e val[e] * ego[col[e]]
// ---------------------------------------------------------------------------
__global__ __launch_bounds__(256)
void gather_spmm_kernel(const float* __restrict__ ego) {
    const int wid  = (blockIdx.x * blockDim.x + threadIdx.x) >> 5;
    const int lane = threadIdx.x & 31;
    if (wid >= N_NODES) return;

    const int start = g_start[wid];
    const int cnt   = g_cnt[wid];

    float4 acc = make_float4(0.f, 0.f, 0.f, 0.f);

    for (int j0 = 0; j0 < cnt; j0 += 32) {
        const int rem = min(32, cnt - j0);
        int   myc = 0;
        float myv = 0.f;
        if (lane < rem) {
            myc = __ldg(g_ecol + start + j0 + lane);
            myv = __ldg(g_eval + start + j0 + lane);
        }
        int kk = 0;
        for (; kk + 4 <= rem; kk += 4) {
            const int   c0 = __shfl_sync(0xffffffffu, myc, kk + 0);
            const int   c1 = __shfl_sync(0xffffffffu, myc, kk + 1);
            const int   c2 = __shfl_sync(0xffffffffu, myc, kk + 2);
            const int   c3 = __shfl_sync(0xffffffffu, myc, kk + 3);
            const float v0 = __shfl_sync(0xffffffffu, myv, kk + 0);
            const float v1 = __shfl_sync(0xffffffffu, myv, kk + 1);
            const float v2 = __shfl_sync(0xffffffffu, myv, kk + 2);
            const float v3 = __shfl_sync(0xffffffffu, myv, kk + 3);
            const float4 e0 = __ldg(reinterpret_cast<const float4*>(ego + (size_t)c0 * DIM) + lane);
            const float4 e1 = __ldg(reinterpret_cast<const float4*>(ego + (size_t)c1 * DIM) + lane);
            const float4 e2 = __ldg(reinterpret_cast<const float4*>(ego + (size_t)c2 * DIM) + lane);
            const float4 e3 = __ldg(reinterpret_cast<const float4*>(ego + (size_t)c3 * DIM) + lane);
            acc.x = fmaf(v0, e0.x, acc.x); acc.y = fmaf(v0, e0.y, acc.y);
            acc.z = fmaf(v0, e0.z, acc.z); acc.w = fmaf(v0, e0.w, acc.w);
            acc.x = fmaf(v1, e1.x, acc.x); acc.y = fmaf(v1, e1.y, acc.y);
            acc.z = fmaf(v1, e1.z, acc.z); acc.w = fmaf(v1, e1.w, acc.w);
            acc.x = fmaf(v2, e2.x, acc.x); acc.y = fmaf(v2, e2.y, acc.y);
            acc.z = fmaf(v2, e2.z, acc.z); acc.w = fmaf(v2, e2.w, acc.w);
            acc.x = fmaf(v3, e3.x, acc.x); acc.y = fmaf(v3, e3.y, acc.y);
            acc.z = fmaf(v3, e3.z, acc.z); acc.w = fmaf(v3, e3.w, acc.w);
        }
        for (; kk < rem; kk++) {
            const int   c = __shfl_sync(0xffffffffu, myc, kk);
            const float v = __shfl_sync(0xffffffffu, myv, kk);
            const float4 e = __ldg(reinterpret_cast<const float4*>(ego + (size_t)c * DIM) + lane);
            acc.x = fmaf(v, e.x, acc.x); acc.y = fmaf(v, e.y, acc.y);
            acc.z = fmaf(v, e.z, acc.z); acc.w = fmaf(v, e.w, acc.w);
        }
    }
    reinterpret_cast<float4*>(g_side + (size_t)wid * DIM)[lane] = acc;
}

// ---------------------------------------------------------------------------
// Fused dense via mma.sync (bf16x3 split == ~fp32):
//   X1 = (1-a)*(ego+side)+a*h0 ; X2 = (1-a)*(ego*side)+a*h0
//   D_b = X@M_b ~= Xh@Bh + Xl@Bh + Xh@Bl
//   out = lrelu(D1+b1) + lrelu(D2+b2)
// CTA: 256 threads, 128-row tile; each warp owns 16 rows.
// smem: Ah,Al + B1h,B1l,B2h,B2l, each 128 x TSTRIDE bf16.
// ---------------------------------------------------------------------------
#define FM_THREADS 256

extern __shared__ __nv_bfloat16 fm_smem[];

__device__ __forceinline__ void build_x_tile(__nv_bfloat16* sAh, __nv_bfloat16* sAl,
                                             const float* __restrict__ ego,
                                             const float* __restrict__ h0,
                                             int row0, int tid, bool mul) {
#pragma unroll
    for (int i = tid; i < 128 * 32; i += FM_THREADS) {
        const int r  = i >> 5;
        const int c4 = i & 31;
        const int grow = row0 + r;
        float v[4] = {0.f, 0.f, 0.f, 0.f};
        if (grow < N_NODES) {
            const float4 e = __ldg(reinterpret_cast<const float4*>(ego + (size_t)grow * DIM) + c4);
            const float4 s = *(reinterpret_cast<const float4*>(g_side + (size_t)grow * DIM) + c4);
            const float4 h = __ldg(reinterpret_cast<const float4*>(h0 + (size_t)grow * DIM) + c4);
            const float oa = 1.0f - ALPHA_C;
            if (!mul) {
                v[0] = oa * (e.x + s.x) + ALPHA_C * h.x;
                v[1] = oa * (e.y + s.y) + ALPHA_C * h.y;
                v[2] = oa * (e.z + s.z) + ALPHA_C * h.z;
                v[3] = oa * (e.w + s.w) + ALPHA_C * h.w;
            } else {
                v[0] = oa * (e.x * s.x) + ALPHA_C * h.x;
                v[1] = oa * (e.y * s.y) + ALPHA_C * h.y;
                v[2] = oa * (e.z * s.z) + ALPHA_C * h.z;
                v[3] = oa * (e.w * s.w) + ALPHA_C * h.w;
            }
        }
        __nv_bfloat162 hh[2], ll[2];
#pragma unroll
        for (int j = 0; j < 2; j++) {
            const __nv_bfloat16 h0b = __float2bfloat16(v[j * 2 + 0]);
            const __nv_bfloat16 h1b = __float2bfloat16(v[j * 2 + 1]);
            hh[j] = __halves2bfloat162(h0b, h1b);
            ll[j] = __halves2bfloat162(__float2bfloat16(v[j * 2 + 0] - __bfloat162float(h0b)),
                                       __float2bfloat16(v[j * 2 + 1] - __bfloat162float(h1b)));
        }
        const int idx = r * TSTRIDE + c4 * 4;
        *reinterpret_cast<__nv_bfloat162*>(sAh + idx)     = hh[0];
        *reinterpret_cast<__nv_bfloat162*>(sAh + idx + 2) = hh[1];
        *reinterpret_cast<__nv_bfloat162*>(sAl + idx)     = ll[0];
        *reinterpret_cast<__nv_bfloat162*>(sAl + idx + 2) = ll[1];
    }
}

// One branch mainloop: acc[64] covers 16 rows x 128 cols for this warp.
__device__ __forceinline__ void run_branch(uint32_t aH, uint32_t aL,
                                           uint32_t bH, uint32_t bL,
                                           float* acc) {
#pragma unroll
    for (int i = 0; i < 64; i++) acc[i] = 0.f;
    for (int ks = 0; ks < 8; ks++) {
        const uint32_t ko = (uint32_t)ks * 32;   // k0*2 bytes (k0 = 16*ks)
        uint32_t ah[4], al[4];
        ldmat_x4(ah, aH + ko);
        ldmat_x4(al, aL + ko);
#pragma unroll
        for (int np = 0; np < 8; np++) {
            uint32_t bh[4], bl[4];
            const uint32_t bo = (uint32_t)np * (16 * TSTRIDE * 2) + ko;
            ldmat_x4(bh, bH + bo);
            ldmat_x4(bl, bL + bo);
            float* a0 = acc + np * 8;
            mma_bf16(a0,     ah, bh);
            mma_bf16(a0 + 4, ah, bh + 2);
            mma_bf16(a0,     al, bh);
            mma_bf16(a0 + 4, al, bh + 2);
            mma_bf16(a0,     ah, bl);
            mma_bf16(a0 + 4, ah, bl + 2);
        }
    }
}

__global__ __launch_bounds__(FM_THREADS, 1)
void fused_mma_kernel(const float* __restrict__ ego,
                      const float* __restrict__ h0,
                      const float* __restrict__ b1,
                      const float* __restrict__ b2,
                      float* __restrict__ out) {
    __shared__ float sb1[DIM], sb2[DIM];

    __nv_bfloat16* sAh  = fm_smem;
    __nv_bfloat16* sAl  = sAh + TILE_ELEMS;
    __nv_bfloat16* sB   = sAl + TILE_ELEMS;   // 4 contiguous images

    const int tid  = threadIdx.x;
    const int lane = tid & 31;
    const int w    = tid >> 5;
    const int row0 = blockIdx.x * 128;

    if (tid < DIM) { sb1[tid] = b1[tid]; sb2[tid] = b2[tid]; }

    // Copy all 4 packed B images (139264 B) as uint4
    {
        const uint4* g = reinterpret_cast<const uint4*>(g_Bpack);
        uint4* d = reinterpret_cast<uint4*>(sB);
#pragma unroll
        for (int i = tid; i < 4 * TILE_BYTES / 16; i += FM_THREADS) d[i] = __ldg(g + i);
    }

    build_x_tile(sAh, sAl, ego, h0, row0, tid, false);
    __syncthreads();

    // Per-thread ldmatrix base addresses
    const uint32_t aRowByte = (uint32_t)((w * 16 + (lane & 15)) * (TSTRIDE * 2) + ((lane >> 4) & 1) * 16);
    const uint32_t bRowByte = (uint32_t)((((lane & 7) + ((lane >> 4) << 3)) * (TSTRIDE * 2)) + ((lane >> 3) & 1) * 16);
    const uint32_t aH = smem_u32(sAh) + aRowByte;
    const uint32_t aL = smem_u32(sAl) + aRowByte;
    const uint32_t b1H = smem_u32(sB) + 0 * TILE_BYTES + bRowByte;
    const uint32_t b1L = smem_u32(sB) + 1 * TILE_BYTES + bRowByte;
    const uint32_t b2H = smem_u32(sB) + 2 * TILE_BYTES + bRowByte;
    const uint32_t b2L = smem_u32(sB) + 3 * TILE_BYTES + bRowByte;

    float acc[64], r1[64];

    // Branch 1
    run_branch(aH, aL, b1H, b1L, acc);
    {
        const int c0 = (lane & 3) * 2;
#pragma unroll
        for (int nt = 0; nt < 16; nt++) {
            const int c = nt * 8 + c0;
            const float bb0 = sb1[c], bbv = sb1[c + 1];
            r1[nt * 4 + 0] = lrelu(acc[nt * 4 + 0] + bb0);
            r1[nt * 4 + 1] = lrelu(acc[nt * 4 + 1] + bbv);
            r1[nt * 4 + 2] = lrelu(acc[nt * 4 + 2] + bb0);
            r1[nt * 4 + 3] = lrelu(acc[nt * 4 + 3] + bbv);
        }
    }
    __syncthreads();               // all warps done reading A before rebuild

    // Branch 2
    build_x_tile(sAh, sAl, ego, h0, row0, tid, true);
    __syncthreads();
    run_branch(aH, aL, b2H, b2L, acc);

    // Epilogue
    {
        const int c0 = (lane & 3) * 2;
        const int rlow  = row0 + w * 16 + (lane >> 2);
        const int rhigh = rlow + 8;
#pragma unroll
        for (int nt = 0; nt < 16; nt++) {
            const int c = nt * 8 + c0;
            const float bb0 = sb2[c], bbv = sb2[c + 1];
            if (rlow < N_NODES) {
                float2 o;
                o.x = r1[nt * 4 + 0] + lrelu(acc[nt * 4 + 0] + bb0);
                o.y = r1[nt * 4 + 1] + lrelu(acc[nt * 4 + 1] + bbv);
                *reinterpret_cast<float2*>(out + (size_t)rlow * DIM + c) = o;
            }
            if (rhigh < N_NODES) {
                float2 o;
                o.x = r1[nt * 4 + 2] + lrelu(acc[nt * 4 + 2] + bb0);
                o.y = r1[nt * 4 + 3] + lrelu(acc[nt * 4 + 3] + bbv);
                *reinterpret_cast<float2*>(out + (size_t)rhigh * DIM + c) = o;
            }
        }
    }
}

// ---------------------------------------------------------------------------
// Launch
// Inputs: 0=ego 1=h0 2=vals 3=weight 4=w1 5=b1 6=w2 7=b2 8=row 9=col
// ---------------------------------------------------------------------------
extern "C" void kernel_launch(void* const* d_in, const int* in_sizes, int n_in,
                              void* d_out, int out_size) {
    const float* ego    = (const float*)d_in[0];
    const float* h0     = (const float*)d_in[1];
    const float* vals   = (const float*)d_in[2];
    const float* weight = (const float*)d_in[3];
    const float* w1     = (const float*)d_in[4];
    const float* b1     = (const float*)d_in[5];
    const float* w2     = (const float*)d_in[6];
    const float* b2     = (const float*)d_in[7];
    const int*   row    = (const int*)d_in[8];
    const int*   col    = (const int*)d_in[9];
    float* out = (float*)d_out;

    const int E = in_sizes[2];

    // Fold + pack weight matrices
    compute_M_kernel<<<DIM, DIM>>>(weight, w1, w2);

    // CSR build
    zero_cnt_kernel<<<(N_NODES + 255) / 256, 256>>>();
    hist_kernel<<<(E + 255) / 256, 256>>>(row, E);
    scan1_kernel<<<NB_SCAN, SCAN_B>>>();
    scan2_kernel<<<1, 128>>>();
    scan3_kernel<<<(N_NODES + 255) / 256, 256>>>();
    scatter_kernel<<<(E + 255) / 256, 256>>>(row, col, vals, E);

    // Gather SpMM
    {
        const int warps_per_block = 8;
        const int blocks = (N_NODES + warps_per_block - 1) / warps_per_block;
        gather_spmm_kernel<<<blocks, warps_per_block * 32>>>(ego);
    }

    // Fused dense via mma.sync
    {
        const int smem_bytes = 6 * TILE_BYTES;   // 208896
        cudaFuncSetAttribute(fused_mma_kernel, cudaFuncAttributeMaxDynamicSharedMemorySize, smem_bytes);
        const int blocks = (N_NODES + 127) / 128;   // 782
        fused_mma_kernel<<<blocks, FM_THREADS, smem_bytes>>>(ego, h0, b1, b2, out);
    }
}

// round 7
// speedup vs baseline: 1.9025x; 1.1016x over previous
#include <cuda_runtime.h>
#include <cuda_bf16.h>
#include <cstdint>

#define N_NODES 100000
#define DIM     128
#define ALPHA_C 0.1f
#define BETA_C  0.4054651081081644f   // ln(1.5)
#define EMAX    3200000
#define SCAN_B  1024
#define NB_SCAN ((N_NODES + SCAN_B - 1) / SCAN_B)   // 98

// Padded bf16 tile layout: row stride 136 elements (272 bytes, 16B-aligned,
// conflict-free for ldmatrix)
#define TSTRIDE 136
#define TILE_ELEMS (DIM * TSTRIDE)          // 17408 bf16 per image
#define TILE_BYTES (TILE_ELEMS * 2)         // 34816 B

// ---------------------------------------------------------------------------
// Device scratch (allocation is forbidden)
// ---------------------------------------------------------------------------
__device__ __align__(256) float g_side[(size_t)N_NODES * DIM];
__device__ __align__(256) int   g_cnt[N_NODES];
__device__ __align__(256) int   g_scan[N_NODES];
__device__ __align__(256) int   g_start[N_NODES];
__device__ __align__(256) int   g_cursor[N_NODES];
__device__ __align__(256) int   g_bsum[SCAN_B];
__device__ __align__(256) int   g_boff[SCAN_B];
__device__ __align__(256) int   g_ecol[EMAX];
__device__ __align__(256) float g_eval[EMAX];
// Packed B images: [0]=B1h [1]=B1l [2]=B2h [3]=B2l, each [n][k] stride TSTRIDE
__device__ __align__(256) __nv_bfloat16 g_Bpack[4 * TILE_ELEMS];

// ---------------------------------------------------------------------------
// PTX helpers: ldmatrix + bf16 mma (target-portable on compute_103)
// ---------------------------------------------------------------------------
__device__ __forceinline__ uint32_t smem_u32(const void* p) {
    uint32_t a;
    asm("{ .reg .u64 t; cvta.to.shared.u64 t, %1; cvt.u32.u64 %0, t; }" : "=r"(a) : "l"(p));
    return a;
}
__device__ __forceinline__ void ldmat_x4(uint32_t* r, uint32_t addr) {
    asm volatile("ldmatrix.sync.aligned.m8n8.x4.shared.b16 {%0,%1,%2,%3}, [%4];"
                 : "=r"(r[0]), "=r"(r[1]), "=r"(r[2]), "=r"(r[3]) : "r"(addr));
}
__device__ __forceinline__ void mma_bf16(float* d, const uint32_t* a, const uint32_t* b) {
    asm volatile(
        "mma.sync.aligned.m16n8k16.row.col.f32.bf16.bf16.f32 "
        "{%0,%1,%2,%3},{%4,%5,%6,%7},{%8,%9},{%0,%1,%2,%3};"
        : "+f"(d[0]), "+f"(d[1]), "+f"(d[2]), "+f"(d[3])
        : "r"(a[0]), "r"(a[1]), "r"(a[2]), "r"(a[3]), "r"(b[0]), "r"(b[1]));
}

__device__ __forceinline__ float lrelu(float x) { return fmaxf(x, 0.01f * x); }

// ---------------------------------------------------------------------------
// compute_M: M1 = im@w1, M2 = im@w2 (im = (1-beta)+beta*weight); store
// transposed hi/lo bf16 into padded [n][k] images.
// ---------------------------------------------------------------------------
__global__ void compute_M_kernel(const float* __restrict__ weight,
                                 const float* __restrict__ w1,
                                 const float* __restrict__ w2) {
    __shared__ float sIm[DIM];
    const int i = blockIdx.x;   // k
    const int j = threadIdx.x;  // n
    sIm[j] = (1.0f - BETA_C) + BETA_C * weight[i * DIM + j];
    __syncthreads();
    float a1 = 0.0f, a2 = 0.0f;
#pragma unroll 8
    for (int k = 0; k < DIM; k++) {
        const float im = sIm[k];
        a1 = fmaf(im, __ldg(w1 + k * DIM + j), a1);
        a2 = fmaf(im, __ldg(w2 + k * DIM + j), a2);
    }
    const __nv_bfloat16 h1 = __float2bfloat16(a1);
    const __nv_bfloat16 l1 = __float2bfloat16(a1 - __bfloat162float(h1));
    const __nv_bfloat16 h2 = __float2bfloat16(a2);
    const __nv_bfloat16 l2 = __float2bfloat16(a2 - __bfloat162float(h2));
    const int base = j * TSTRIDE + i;    // [n][k]
    g_Bpack[0 * TILE_ELEMS + base] = h1;
    g_Bpack[1 * TILE_ELEMS + base] = l1;
    g_Bpack[2 * TILE_ELEMS + base] = h2;
    g_Bpack[3 * TILE_ELEMS + base] = l2;
}

// ---------------------------------------------------------------------------
// CSR build
// ---------------------------------------------------------------------------
__global__ void zero_cnt_kernel() {
    const int i = blockIdx.x * blockDim.x + threadIdx.x;
    if (i < N_NODES) g_cnt[i] = 0;
}
__global__ void hist_kernel(const int* __restrict__ row, int E) {
    const int e = blockIdx.x * blockDim.x + threadIdx.x;
    if (e < E) atomicAdd(&g_cnt[__ldg(row + e)], 1);
}
__global__ void scan1_kernel() {
    __shared__ int s[SCAN_B];
    const int tid = threadIdx.x;
    const int i = blockIdx.x * SCAN_B + tid;
    int v = (i < N_NODES) ? g_cnt[i] : 0;
    s[tid] = v;
    __syncthreads();
#pragma unroll
    for (int off = 1; off < SCAN_B; off <<= 1) {
        int t = (tid >= off) ? s[tid - off] : 0;
        __syncthreads();
        s[tid] += t;
        __syncthreads();
    }
    if (i < N_NODES) g_scan[i] = s[tid];
    if (tid == SCAN_B - 1) g_bsum[blockIdx.x] = s[tid];
}
__global__ void scan2_kernel() {
    __shared__ int s[128];
    const int tid = threadIdx.x;
    int v = (tid < NB_SCAN) ? g_bsum[tid] : 0;
    s[tid] = v;
    __syncthreads();
#pragma unroll
    for (int off = 1; off < 128; off <<= 1) {
        int t = (tid >= off) ? s[tid - off] : 0;
        __syncthreads();
        s[tid] += t;
        __syncthreads();
    }
    if (tid < NB_SCAN) g_boff[tid] = s[tid] - v;
}
__global__ void scan3_kernel() {
    const int i = blockIdx.x * blockDim.x + threadIdx.x;
    if (i < N_NODES) {
        const int excl = g_scan[i] - g_cnt[i] + g_boff[i / SCAN_B];
        g_start[i]  = excl;
        g_cursor[i] = excl;
    }
}
__global__ void scatter_kernel(const int* __restrict__ row,
                               const int* __restrict__ col,
                               const float* __restrict__ vals, int E) {
    const int e = blockIdx.x * blockDim.x + threadIdx.x;
    if (e < E) {
        const int r = __ldg(row + e);
        const int pos = atomicAdd(&g_cursor[r], 1);
        g_ecol[pos] = __ldg(col + e);
        g_eval[pos] = __ldg(vals + e);
    }
}

// ---------------------------------------------------------------------------
// Gather SpMM: one warp per row. side[r] = sum_e val[e] * ego[col[e]]
// ---------------------------------------------------------------------------
__global__ __launch_bounds__(256)
void gather_spmm_kernel(const float* __restrict__ ego) {
    const int wid  = (blockIdx.x * blockDim.x + threadIdx.x) >> 5;
    const int lane = threadIdx.x & 31;
    if (wid >= N_NODES) return;

    const int start = g_start[wid];
    const int cnt   = g_cnt[wid];

    float4 acc = make_float4(0.f, 0.f, 0.f, 0.f);

    for (int j0 = 0; j0 < cnt; j0 += 32) {
        const int rem = min(32, cnt - j0);
        int   myc = 0;
        float myv = 0.f;
        if (lane < rem) {
            myc = __ldg(g_ecol + start + j0 + lane);
            myv = __ldg(g_eval + start + j0 + lane);
        }
        int kk = 0;
        for (; kk + 4 <= rem; kk += 4) {
            const int   c0 = __shfl_sync(0xffffffffu, myc, kk + 0);
            const int   c1 = __shfl_sync(0xffffffffu, myc, kk + 1);
            const int   c2 = __shfl_sync(0xffffffffu, myc, kk + 2);
            const int   c3 = __shfl_sync(0xffffffffu, myc, kk + 3);
            const float v0 = __shfl_sync(0xffffffffu, myv, kk + 0);
            const float v1 = __shfl_sync(0xffffffffu, myv, kk + 1);
            const float v2 = __shfl_sync(0xffffffffu, myv, kk + 2);
            const float v3 = __shfl_sync(0xffffffffu, myv, kk + 3);
            const float4 e0 = __ldg(reinterpret_cast<const float4*>(ego + (size_t)c0 * DIM) + lane);
            const float4 e1 = __ldg(reinterpret_cast<const float4*>(ego + (size_t)c1 * DIM) + lane);
            const float4 e2 = __ldg(reinterpret_cast<const float4*>(ego + (size_t)c2 * DIM) + lane);
            const float4 e3 = __ldg(reinterpret_cast<const float4*>(ego + (size_t)c3 * DIM) + lane);
            acc.x = fmaf(v0, e0.x, acc.x); acc.y = fmaf(v0, e0.y, acc.y);
            acc.z = fmaf(v0, e0.z, acc.z); acc.w = fmaf(v0, e0.w, acc.w);
            acc.x = fmaf(v1, e1.x, acc.x); acc.y = fmaf(v1, e1.y, acc.y);
            acc.z = fmaf(v1, e1.z, acc.z); acc.w = fmaf(v1, e1.w, acc.w);
            acc.x = fmaf(v2, e2.x, acc.x); acc.y = fmaf(v2, e2.y, acc.y);
            acc.z = fmaf(v2, e2.z, acc.z); acc.w = fmaf(v2, e2.w, acc.w);
            acc.x = fmaf(v3, e3.x, acc.x); acc.y = fmaf(v3, e3.y, acc.y);
            acc.z = fmaf(v3, e3.z, acc.z); acc.w = fmaf(v3, e3.w, acc.w);
        }
        for (; kk < rem; kk++) {
            const int   c = __shfl_sync(0xffffffffu, myc, kk);
            const float v = __shfl_sync(0xffffffffu, myv, kk);
            const float4 e = __ldg(reinterpret_cast<const float4*>(ego + (size_t)c * DIM) + lane);
            acc.x = fmaf(v, e.x, acc.x); acc.y = fmaf(v, e.y, acc.y);
            acc.z = fmaf(v, e.z, acc.z); acc.w = fmaf(v, e.w, acc.w);
        }
    }
    reinterpret_cast<float4*>(g_side + (size_t)wid * DIM)[lane] = acc;
}

// ---------------------------------------------------------------------------
// Fused dense via mma.sync (bf16x3 split == ~fp32), 512 threads / CTA.
// 128-row tile; 16 warps, N-split: warps 0-7 -> cols 0-63, 8-15 -> cols 64-127.
// Each warp: 16 rows x 64 cols (acc[32]).
// ---------------------------------------------------------------------------
#define FM_THREADS 512

extern __shared__ __nv_bfloat16 fm_smem[];

__device__ __forceinline__ void build_x_tile(__nv_bfloat16* sAh, __nv_bfloat16* sAl,
                                             const float* __restrict__ ego,
                                             const float* __restrict__ h0,
                                             int row0, int tid, bool mul) {
#pragma unroll
    for (int i = tid; i < 128 * 32; i += FM_THREADS) {
        const int r  = i >> 5;
        const int c4 = i & 31;
        const int grow = row0 + r;
        float v[4] = {0.f, 0.f, 0.f, 0.f};
        if (grow < N_NODES) {
            const float4 e = __ldg(reinterpret_cast<const float4*>(ego + (size_t)grow * DIM) + c4);
            const float4 s = *(reinterpret_cast<const float4*>(g_side + (size_t)grow * DIM) + c4);
            const float4 h = __ldg(reinterpret_cast<const float4*>(h0 + (size_t)grow * DIM) + c4);
            const float oa = 1.0f - ALPHA_C;
            if (!mul) {
                v[0] = oa * (e.x + s.x) + ALPHA_C * h.x;
                v[1] = oa * (e.y + s.y) + ALPHA_C * h.y;
                v[2] = oa * (e.z + s.z) + ALPHA_C * h.z;
                v[3] = oa * (e.w + s.w) + ALPHA_C * h.w;
            } else {
                v[0] = oa * (e.x * s.x) + ALPHA_C * h.x;
                v[1] = oa * (e.y * s.y) + ALPHA_C * h.y;
                v[2] = oa * (e.z * s.z) + ALPHA_C * h.z;
                v[3] = oa * (e.w * s.w) + ALPHA_C * h.w;
            }
        }
        __nv_bfloat162 hh[2], ll[2];
#pragma unroll
        for (int j = 0; j < 2; j++) {
            const __nv_bfloat16 h0b = __float2bfloat16(v[j * 2 + 0]);
            const __nv_bfloat16 h1b = __float2bfloat16(v[j * 2 + 1]);
            hh[j] = __halves2bfloat162(h0b, h1b);
            ll[j] = __halves2bfloat162(__float2bfloat16(v[j * 2 + 0] - __bfloat162float(h0b)),
                                       __float2bfloat16(v[j * 2 + 1] - __bfloat162float(h1b)));
        }
        const int idx = r * TSTRIDE + c4 * 4;
        *reinterpret_cast<__nv_bfloat162*>(sAh + idx)     = hh[0];
        *reinterpret_cast<__nv_bfloat162*>(sAh + idx + 2) = hh[1];
        *reinterpret_cast<__nv_bfloat162*>(sAl + idx)     = ll[0];
        *reinterpret_cast<__nv_bfloat162*>(sAl + idx + 2) = ll[1];
    }
}

// One branch mainloop: acc[32] covers 16 rows x 64 cols for this warp.
__device__ __forceinline__ void run_branch(uint32_t aH, uint32_t aL,
                                           uint32_t bH, uint32_t bL,
                                           float* acc) {
#pragma unroll
    for (int i = 0; i < 32; i++) acc[i] = 0.f;
    for (int ks = 0; ks < 8; ks++) {
        const uint32_t ko = (uint32_t)ks * 32;   // 16 k-elems * 2B
        uint32_t ah[4], al[4];
        ldmat_x4(ah, aH + ko);
        ldmat_x4(al, aL + ko);
#pragma unroll
        for (int np = 0; np < 4; np++) {
            uint32_t bh[4], bl[4];
            const uint32_t bo = (uint32_t)np * (16 * TSTRIDE * 2) + ko;
            ldmat_x4(bh, bH + bo);
            ldmat_x4(bl, bL + bo);
            float* a0 = acc + np * 8;
            mma_bf16(a0,     ah, bh);
            mma_bf16(a0 + 4, ah, bh + 2);
            mma_bf16(a0,     al, bh);
            mma_bf16(a0 + 4, al, bh + 2);
            mma_bf16(a0,     ah, bl);
            mma_bf16(a0 + 4, ah, bl + 2);
        }
    }
}

__global__ __launch_bounds__(FM_THREADS, 1)
void fused_mma_kernel(const float* __restrict__ ego,
                      const float* __restrict__ h0,
                      const float* __restrict__ b1,
                      const float* __restrict__ b2,
                      float* __restrict__ out) {
    __shared__ float sb1[DIM], sb2[DIM];

    __nv_bfloat16* sAh  = fm_smem;
    __nv_bfloat16* sAl  = sAh + TILE_ELEMS;
    __nv_bfloat16* sB   = sAl + TILE_ELEMS;   // 4 contiguous images

    const int tid  = threadIdx.x;
    const int lane = tid & 31;
    const int w    = tid >> 5;          // 0..15
    const int wr   = w & 7;             // row-group (16 rows)
    const int wn   = w >> 3;            // n-half (64 cols)
    const int row0 = blockIdx.x * 128;

    if (tid < DIM) { sb1[tid] = b1[tid]; sb2[tid] = b2[tid]; }

    // Copy all 4 packed B images (139264 B) as uint4
    {
        const uint4* g = reinterpret_cast<const uint4*>(g_Bpack);
        uint4* d = reinterpret_cast<uint4*>(sB);
#pragma unroll
        for (int i = tid; i < 4 * TILE_BYTES / 16; i += FM_THREADS) d[i] = __ldg(g + i);
    }

    build_x_tile(sAh, sAl, ego, h0, row0, tid, false);
    __syncthreads();

    // Per-thread ldmatrix base addresses
    const uint32_t aRowByte = (uint32_t)((wr * 16 + (lane & 15)) * (TSTRIDE * 2) + ((lane >> 4) & 1) * 16);
    const uint32_t bRowByte = (uint32_t)((wn * 64 + (lane & 7) + ((lane >> 4) << 3)) * (TSTRIDE * 2) + ((lane >> 3) & 1) * 16);
    const uint32_t aH = smem_u32(sAh) + aRowByte;
    const uint32_t aL = smem_u32(sAl) + aRowByte;
    const uint32_t b1H = smem_u32(sB) + 0 * TILE_BYTES + bRowByte;
    const uint32_t b1L = smem_u32(sB) + 1 * TILE_BYTES + bRowByte;
    const uint32_t b2H = smem_u32(sB) + 2 * TILE_BYTES + bRowByte;
    const uint32_t b2L = smem_u32(sB) + 3 * TILE_BYTES + bRowByte;

    float acc[32], r1[32];

    // Branch 1
    run_branch(aH, aL, b1H, b1L, acc);
    {
        const int c0 = wn * 64 + (lane & 3) * 2;
#pragma unroll
        for (int nt = 0; nt < 8; nt++) {
            const int c = nt * 8 + c0;
            const float bb0 = sb1[c], bbv = sb1[c + 1];
            r1[nt * 4 + 0] = lrelu(acc[nt * 4 + 0] + bb0);
            r1[nt * 4 + 1] = lrelu(acc[nt * 4 + 1] + bbv);
            r1[nt * 4 + 2] = lrelu(acc[nt * 4 + 2] + bb0);
            r1[nt * 4 + 3] = lrelu(acc[nt * 4 + 3] + bbv);
        }
    }
    __syncthreads();               // all warps done reading A before rebuild

    // Branch 2
    build_x_tile(sAh, sAl, ego, h0, row0, tid, true);
    __syncthreads();
    run_branch(aH, aL, b2H, b2L, acc);

    // Epilogue
    {
        const int c0 = wn * 64 + (lane & 3) * 2;
        const int rlow  = row0 + wr * 16 + (lane >> 2);
        const int rhigh = rlow + 8;
#pragma unroll
        for (int nt = 0; nt < 8; nt++) {
            const int c = nt * 8 + c0;
            const float bb0 = sb2[c], bbv = sb2[c + 1];
            if (rlow < N_NODES) {
                float2 o;
                o.x = r1[nt * 4 + 0] + lrelu(acc[nt * 4 + 0] + bb0);
                o.y = r1[nt * 4 + 1] + lrelu(acc[nt * 4 + 1] + bbv);
                *reinterpret_cast<float2*>(out + (size_t)rlow * DIM + c) = o;
            }
            if (rhigh < N_NODES) {
                float2 o;
                o.x = r1[nt * 4 + 2] + lrelu(acc[nt * 4 + 2] + bb0);
                o.y = r1[nt * 4 + 3] + lrelu(acc[nt * 4 + 3] + bbv);
                *reinterpret_cast<float2*>(out + (size_t)rhigh * DIM + c) = o;
            }
        }
    }
}

// ---------------------------------------------------------------------------
// Launch
// Inputs: 0=ego 1=h0 2=vals 3=weight 4=w1 5=b1 6=w2 7=b2 8=row 9=col
// ---------------------------------------------------------------------------
extern "C" void kernel_launch(void* const* d_in, const int* in_sizes, int n_in,
                              void* d_out, int out_size) {
    const float* ego    = (const float*)d_in[0];
    const float* h0     = (const float*)d_in[1];
    const float* vals   = (const float*)d_in[2];
    const float* weight = (const float*)d_in[3];
    const float* w1     = (const float*)d_in[4];
    const float* b1     = (const float*)d_in[5];
    const float* w2     = (const float*)d_in[6];
    const float* b2     = (const float*)d_in[7];
    const int*   row    = (const int*)d_in[8];
    const int*   col    = (const int*)d_in[9];
    float* out = (float*)d_out;

    const int E = in_sizes[2];

    // Fold + pack weight matrices
    compute_M_kernel<<<DIM, DIM>>>(weight, w1, w2);

    // CSR build
    zero_cnt_kernel<<<(N_NODES + 255) / 256, 256>>>();
    hist_kernel<<<(E + 255) / 256, 256>>>(row, E);
    scan1_kernel<<<NB_SCAN, SCAN_B>>>();
    scan2_kernel<<<1, 128>>>();
    scan3_kernel<<<(N_NODES + 255) / 256, 256>>>();
    scatter_kernel<<<(E + 255) / 256, 256>>>(row, col, vals, E);

    // Gather SpMM
    {
        const int warps_per_block = 8;
        const int blocks = (N_NODES + warps_per_block - 1) / warps_per_block;
        gather_spmm_kernel<<<blocks, warps_per_block * 32>>>(ego);
    }

    // Fused dense via mma.sync
    {
        const int smem_bytes = 6 * TILE_BYTES;   // 208896
        cudaFuncSetAttribute(fused_mma_kernel, cudaFuncAttributeMaxDynamicSharedMemorySize, smem_bytes);
        const int blocks = (N_NODES + 127) / 128;   // 782
        fused_mma_kernel<<<blocks, FM_THREADS, smem_bytes>>>(ego, h0, b1, b2, out);
    }
}

// round 9
// speedup vs baseline: 1.9468x; 1.0233x over previous
#include <cuda_runtime.h>
#include <cuda_bf16.h>
#include <cstdint>

#define N_NODES 100000
#define DIM     128
#define ALPHA_C 0.1f
#define BETA_C  0.4054651081081644f   // ln(1.5)
#define EMAX    3200000
#define SCAN_B  1024
#define NB_SCAN ((N_NODES + SCAN_B - 1) / SCAN_B)   // 98

// Padded bf16 tile layout: row stride 136 elements (272 bytes, 16B-aligned,
// conflict-free for ldmatrix)
#define TSTRIDE 136
#define TILE_ELEMS (DIM * TSTRIDE)          // 17408 bf16 per image
#define TILE_BYTES (TILE_ELEMS * 2)         // 34816 B

// ---------------------------------------------------------------------------
// Device scratch (allocation is forbidden)
// ---------------------------------------------------------------------------
__device__ __align__(256) float g_side[(size_t)N_NODES * DIM];
__device__ __align__(256) __nv_bfloat16 g_egobf[(size_t)N_NODES * DIM];
__device__ __align__(256) int   g_cnt[N_NODES];
__device__ __align__(256) int   g_scan[N_NODES];
__device__ __align__(256) int   g_start[N_NODES];
__device__ __align__(256) int   g_cursor[N_NODES];
__device__ __align__(256) int   g_bsum[SCAN_B];
__device__ __align__(256) int   g_boff[SCAN_B];
__device__ __align__(256) int   g_ecol[EMAX];
__device__ __align__(256) float g_eval[EMAX];
// Packed B images: [0]=B1h [1]=B1l [2]=B2h [3]=B2l, each [n][k] stride TSTRIDE
__device__ __align__(256) __nv_bfloat16 g_Bpack[4 * TILE_ELEMS];

// ---------------------------------------------------------------------------
// bit-cast helpers (bf16x2 <-> uint32)
// ---------------------------------------------------------------------------
__device__ __forceinline__ uint32_t bf2_to_u32(__nv_bfloat162 v) {
    __nv_bfloat162_raw r = v;
    return (uint32_t)r.x | ((uint32_t)r.y << 16);
}
__device__ __forceinline__ float2 u32_to_f2(uint32_t u) {
    __nv_bfloat162_raw r;
    r.x = (unsigned short)(u & 0xFFFFu);
    r.y = (unsigned short)(u >> 16);
    return __bfloat1622float2(__nv_bfloat162(r));
}

// ---------------------------------------------------------------------------
// PTX helpers: ldmatrix + bf16 mma (target-portable on compute_103)
// ---------------------------------------------------------------------------
__device__ __forceinline__ uint32_t smem_u32(const void* p) {
    uint32_t a;
    asm("{ .reg .u64 t; cvta.to.shared.u64 t, %1; cvt.u32.u64 %0, t; }" : "=r"(a) : "l"(p));
    return a;
}
__device__ __forceinline__ void ldmat_x4(uint32_t* r, uint32_t addr) {
    asm volatile("ldmatrix.sync.aligned.m8n8.x4.shared.b16 {%0,%1,%2,%3}, [%4];"
                 : "=r"(r[0]), "=r"(r[1]), "=r"(r[2]), "=r"(r[3]) : "r"(addr));
}
__device__ __forceinline__ void mma_bf16(float* d, const uint32_t* a, const uint32_t* b) {
    asm volatile(
        "mma.sync.aligned.m16n8k16.row.col.f32.bf16.bf16.f32 "
        "{%0,%1,%2,%3},{%4,%5,%6,%7},{%8,%9},{%0,%1,%2,%3};"
        : "+f"(d[0]), "+f"(d[1]), "+f"(d[2]), "+f"(d[3])
        : "r"(a[0]), "r"(a[1]), "r"(a[2]), "r"(a[3]), "r"(b[0]), "r"(b[1]));
}

__device__ __forceinline__ float lrelu(float x) { return fmaxf(x, 0.01f * x); }

// ---------------------------------------------------------------------------
// compute_M: M1 = im@w1, M2 = im@w2 (im = (1-beta)+beta*weight); store
// transposed hi/lo bf16 into padded [n][k] images.
// ---------------------------------------------------------------------------
__global__ void compute_M_kernel(const float* __restrict__ weight,
                                 const float* __restrict__ w1,
                                 const float* __restrict__ w2) {
    __shared__ float sIm[DIM];
    const int i = blockIdx.x;   // k
    const int j = threadIdx.x;  // n
    sIm[j] = (1.0f - BETA_C) + BETA_C * weight[i * DIM + j];
    __syncthreads();
    float a1 = 0.0f, a2 = 0.0f;
#pragma unroll 8
    for (int k = 0; k < DIM; k++) {
        const float im = sIm[k];
        a1 = fmaf(im, __ldg(w1 + k * DIM + j), a1);
        a2 = fmaf(im, __ldg(w2 + k * DIM + j), a2);
    }
    const __nv_bfloat16 h1 = __float2bfloat16(a1);
    const __nv_bfloat16 l1 = __float2bfloat16(a1 - __bfloat162float(h1));
    const __nv_bfloat16 h2 = __float2bfloat16(a2);
    const __nv_bfloat16 l2 = __float2bfloat16(a2 - __bfloat162float(h2));
    const int base = j * TSTRIDE + i;    // [n][k]
    g_Bpack[0 * TILE_ELEMS + base] = h1;
    g_Bpack[1 * TILE_ELEMS + base] = l1;
    g_Bpack[2 * TILE_ELEMS + base] = h2;
    g_Bpack[3 * TILE_ELEMS + base] = l2;
}

// ---------------------------------------------------------------------------
// ego -> bf16 copy (gather reads half the bytes)
// ---------------------------------------------------------------------------
__global__ void ego_bf16_kernel(const float* __restrict__ ego) {
    const int idx = blockIdx.x * blockDim.x + threadIdx.x;   // one per 8 elems
    const int total = N_NODES * DIM / 8;
    if (idx >= total) return;
    const float4 a = __ldg(reinterpret_cast<const float4*>(ego) + idx * 2);
    const float4 b = __ldg(reinterpret_cast<const float4*>(ego) + idx * 2 + 1);
    uint4 o;
    o.x = bf2_to_u32(__floats2bfloat162_rn(a.x, a.y));
    o.y = bf2_to_u32(__floats2bfloat162_rn(a.z, a.w));
    o.z = bf2_to_u32(__floats2bfloat162_rn(b.x, b.y));
    o.w = bf2_to_u32(__floats2bfloat162_rn(b.z, b.w));
    reinterpret_cast<uint4*>(g_egobf)[idx] = o;
}

// ---------------------------------------------------------------------------
// CSR build
// ---------------------------------------------------------------------------
__global__ void zero_cnt_kernel() {
    const int i = blockIdx.x * blockDim.x + threadIdx.x;
    if (i < N_NODES) g_cnt[i] = 0;
}
__global__ void hist_kernel(const int* __restrict__ row, int E) {
    const int e = blockIdx.x * blockDim.x + threadIdx.x;
    if (e < E) atomicAdd(&g_cnt[__ldg(row + e)], 1);
}
__global__ void scan1_kernel() {
    __shared__ int s[SCAN_B];
    const int tid = threadIdx.x;
    const int i = blockIdx.x * SCAN_B + tid;
    int v = (i < N_NODES) ? g_cnt[i] : 0;
    s[tid] = v;
    __syncthreads();
#pragma unroll
    for (int off = 1; off < SCAN_B; off <<= 1) {
        int t = (tid >= off) ? s[tid - off] : 0;
        __syncthreads();
        s[tid] += t;
        __syncthreads();
    }
    if (i < N_NODES) g_scan[i] = s[tid];
    if (tid == SCAN_B - 1) g_bsum[blockIdx.x] = s[tid];
}
__global__ void scan2_kernel() {
    __shared__ int s[128];
    const int tid = threadIdx.x;
    int v = (tid < NB_SCAN) ? g_bsum[tid] : 0;
    s[tid] = v;
    __syncthreads();
#pragma unroll
    for (int off = 1; off < 128; off <<= 1) {
        int t = (tid >= off) ? s[tid - off] : 0;
        __syncthreads();
        s[tid] += t;
        __syncthreads();
    }
    if (tid < NB_SCAN) g_boff[tid] = s[tid] - v;
}
__global__ void scan3_kernel() {
    const int i = blockIdx.x * blockDim.x + threadIdx.x;
    if (i < N_NODES) {
        const int excl = g_scan[i] - g_cnt[i] + g_boff[i / SCAN_B];
        g_start[i]  = excl;
        g_cursor[i] = excl;
    }
}
__global__ void scatter_kernel(const int* __restrict__ row,
                               const int* __restrict__ col,
                               const float* __restrict__ vals, int E) {
    const int e = blockIdx.x * blockDim.x + threadIdx.x;
    if (e < E) {
        const int r = __ldg(row + e);
        const int pos = atomicAdd(&g_cursor[r], 1);
        g_ecol[pos] = __ldg(col + e);
        g_eval[pos] = __ldg(vals + e);
    }
}

// ---------------------------------------------------------------------------
// Gather SpMM: one warp per row, bf16 ego gather (half the LTS bytes).
// side[r] = sum_e val[e] * ego_bf16[col[e]]   (fp32 accumulate)
// ---------------------------------------------------------------------------
__device__ __forceinline__ void acc_edge(float4& acc, float v, uint2 p) {
    const float2 f0 = u32_to_f2(p.x);
    const float2 f1 = u32_to_f2(p.y);
    acc.x = fmaf(v, f0.x, acc.x);
    acc.y = fmaf(v, f0.y, acc.y);
    acc.z = fmaf(v, f1.x, acc.z);
    acc.w = fmaf(v, f1.y, acc.w);
}

__global__ __launch_bounds__(256)
void gather_spmm_kernel() {
    const int wid  = (blockIdx.x * blockDim.x + threadIdx.x) >> 5;
    const int lane = threadIdx.x & 31;
    if (wid >= N_NODES) return;

    const int start = g_start[wid];
    const int cnt   = g_cnt[wid];

    float4 acc = make_float4(0.f, 0.f, 0.f, 0.f);

    for (int j0 = 0; j0 < cnt; j0 += 32) {
        const int rem = min(32, cnt - j0);
        int   myc = 0;
        float myv = 0.f;
        if (lane < rem) {
            myc = __ldg(g_ecol + start + j0 + lane);
            myv = __ldg(g_eval + start + j0 + lane);
        }
        int kk = 0;
        for (; kk + 4 <= rem; kk += 4) {
            const int   c0 = __shfl_sync(0xffffffffu, myc, kk + 0);
            const int   c1 = __shfl_sync(0xffffffffu, myc, kk + 1);
            const int   c2 = __shfl_sync(0xffffffffu, myc, kk + 2);
            const int   c3 = __shfl_sync(0xffffffffu, myc, kk + 3);
            const float v0 = __shfl_sync(0xffffffffu, myv, kk + 0);
            const float v1 = __shfl_sync(0xffffffffu, myv, kk + 1);
            const float v2 = __shfl_sync(0xffffffffu, myv, kk + 2);
            const float v3 = __shfl_sync(0xffffffffu, myv, kk + 3);
            const uint2 p0 = __ldg(reinterpret_cast<const uint2*>(g_egobf + (size_t)c0 * DIM) + lane);
            const uint2 p1 = __ldg(reinterpret_cast<const uint2*>(g_egobf + (size_t)c1 * DIM) + lane);
            const uint2 p2 = __ldg(reinterpret_cast<const uint2*>(g_egobf + (size_t)c2 * DIM) + lane);
            const uint2 p3 = __ldg(reinterpret_cast<const uint2*>(g_egobf + (size_t)c3 * DIM) + lane);
            acc_edge(acc, v0, p0);
            acc_edge(acc, v1, p1);
            acc_edge(acc, v2, p2);
            acc_edge(acc, v3, p3);
        }
        for (; kk < rem; kk++) {
            const int   c = __shfl_sync(0xffffffffu, myc, kk);
            const float v = __shfl_sync(0xffffffffu, myv, kk);
            const uint2 p = __ldg(reinterpret_cast<const uint2*>(g_egobf + (size_t)c * DIM) + lane);
            acc_edge(acc, v, p);
        }
    }
    // lane covers cols [lane*4, lane*4+4)
    reinterpret_cast<float4*>(g_side + (size_t)wid * DIM)[lane] = acc;
}

// ---------------------------------------------------------------------------
// Fused dense via mma.sync (bf16x3 split == ~fp32), 512 threads / CTA.
// 128-row tile; 16 warps, N-split: warps 0-7 -> cols 0-63, 8-15 -> cols 64-127.
// ---------------------------------------------------------------------------
#define FM_THREADS 512

extern __shared__ __nv_bfloat16 fm_smem[];

__device__ __forceinline__ void build_x_tile(__nv_bfloat16* sAh, __nv_bfloat16* sAl,
                                             const float* __restrict__ ego,
                                             const float* __restrict__ h0,
                                             int row0, int tid, bool mul) {
#pragma unroll
    for (int i = tid; i < 128 * 32; i += FM_THREADS) {
        const int r  = i >> 5;
        const int c4 = i & 31;
        const int grow = row0 + r;
        float v[4] = {0.f, 0.f, 0.f, 0.f};
        if (grow < N_NODES) {
            const float4 e = __ldg(reinterpret_cast<const float4*>(ego + (size_t)grow * DIM) + c4);
            const float4 s = *(reinterpret_cast<const float4*>(g_side + (size_t)grow * DIM) + c4);
            const float4 h = __ldg(reinterpret_cast<const float4*>(h0 + (size_t)grow * DIM) + c4);
            const float oa = 1.0f - ALPHA_C;
            if (!mul) {
                v[0] = oa * (e.x + s.x) + ALPHA_C * h.x;
                v[1] = oa * (e.y + s.y) + ALPHA_C * h.y;
                v[2] = oa * (e.z + s.z) + ALPHA_C * h.z;
                v[3] = oa * (e.w + s.w) + ALPHA_C * h.w;
            } else {
                v[0] = oa * (e.x * s.x) + ALPHA_C * h.x;
                v[1] = oa * (e.y * s.y) + ALPHA_C * h.y;
                v[2] = oa * (e.z * s.z) + ALPHA_C * h.z;
                v[3] = oa * (e.w * s.w) + ALPHA_C * h.w;
            }
        }
        __nv_bfloat162 hh[2], ll[2];
#pragma unroll
        for (int j = 0; j < 2; j++) {
            const __nv_bfloat16 h0b = __float2bfloat16(v[j * 2 + 0]);
            const __nv_bfloat16 h1b = __float2bfloat16(v[j * 2 + 1]);
            hh[j] = __halves2bfloat162(h0b, h1b);
            ll[j] = __halves2bfloat162(__float2bfloat16(v[j * 2 + 0] - __bfloat162float(h0b)),
                                       __float2bfloat16(v[j * 2 + 1] - __bfloat162float(h1b)));
        }
        const int idx = r * TSTRIDE + c4 * 4;
        *reinterpret_cast<__nv_bfloat162*>(sAh + idx)     = hh[0];
        *reinterpret_cast<__nv_bfloat162*>(sAh + idx + 2) = hh[1];
        *reinterpret_cast<__nv_bfloat162*>(sAl + idx)     = ll[0];
        *reinterpret_cast<__nv_bfloat162*>(sAl + idx + 2) = ll[1];
    }
}

// One branch mainloop: acc[32] covers 16 rows x 64 cols for this warp.
__device__ __forceinline__ void run_branch(uint32_t aH, uint32_t aL,
                                           uint32_t bH, uint32_t bL,
                                           float* acc) {
#pragma unroll
    for (int i = 0; i < 32; i++) acc[i] = 0.f;
    for (int ks = 0; ks < 8; ks++) {
        const uint32_t ko = (uint32_t)ks * 32;   // 16 k-elems * 2B
        uint32_t ah[4], al[4];
        ldmat_x4(ah, aH + ko);
        ldmat_x4(al, aL + ko);
#pragma unroll
        for (int np = 0; np < 4; np++) {
            uint32_t bh[4], bl[4];
            const uint32_t bo = (uint32_t)np * (16 * TSTRIDE * 2) + ko;
            ldmat_x4(bh, bH + bo);
            ldmat_x4(bl, bL + bo);
            float* a0 = acc + np * 8;
            mma_bf16(a0,     ah, bh);
            mma_bf16(a0 + 4, ah, bh + 2);
            mma_bf16(a0,     al, bh);
            mma_bf16(a0 + 4, al, bh + 2);
            mma_bf16(a0,     ah, bl);
            mma_bf16(a0 + 4, ah, bl + 2);
        }
    }
}

__global__ __launch_bounds__(FM_THREADS, 1)
void fused_mma_kernel(const float* __restrict__ ego,
                      const float* __restrict__ h0,
                      const float* __restrict__ b1,
                      const float* __restrict__ b2,
                      float* __restrict__ out) {
    __shared__ float sb1[DIM], sb2[DIM];

    __nv_bfloat16* sAh  = fm_smem;
    __nv_bfloat16* sAl  = sAh + TILE_ELEMS;
    __nv_bfloat16* sB   = sAl + TILE_ELEMS;   // 4 contiguous images

    const int tid  = threadIdx.x;
    const int lane = tid & 31;
    const int w    = tid >> 5;          // 0..15
    const int wr   = w & 7;             // row-group (16 rows)
    const int wn   = w >> 3;            // n-half (64 cols)
    const int row0 = blockIdx.x * 128;

    if (tid < DIM) { sb1[tid] = b1[tid]; sb2[tid] = b2[tid]; }

    // Copy all 4 packed B images (139264 B) as uint4
    {
        const uint4* g = reinterpret_cast<const uint4*>(g_Bpack);
        uint4* d = reinterpret_cast<uint4*>(sB);
#pragma unroll
        for (int i = tid; i < 4 * TILE_BYTES / 16; i += FM_THREADS) d[i] = __ldg(g + i);
    }

    build_x_tile(sAh, sAl, ego, h0, row0, tid, false);
    __syncthreads();

    // Per-thread ldmatrix base addresses
    const uint32_t aRowByte = (uint32_t)((wr * 16 + (lane & 15)) * (TSTRIDE * 2) + ((lane >> 4) & 1) * 16);
    const uint32_t bRowByte = (uint32_t)((wn * 64 + (lane & 7) + ((lane >> 4) << 3)) * (TSTRIDE * 2) + ((lane >> 3) & 1) * 16);
    const uint32_t aH = smem_u32(sAh) + aRowByte;
    const uint32_t aL = smem_u32(sAl) + aRowByte;
    const uint32_t b1H = smem_u32(sB) + 0 * TILE_BYTES + bRowByte;
    const uint32_t b1L = smem_u32(sB) + 1 * TILE_BYTES + bRowByte;
    const uint32_t b2H = smem_u32(sB) + 2 * TILE_BYTES + bRowByte;
    const uint32_t b2L = smem_u32(sB) + 3 * TILE_BYTES + bRowByte;

    float acc[32], r1[32];

    // Branch 1
    run_branch(aH, aL, b1H, b1L, acc);
    {
        const int c0 = wn * 64 + (lane & 3) * 2;
#pragma unroll
        for (int nt = 0; nt < 8; nt++) {
            const int c = nt * 8 + c0;
            const float bb0 = sb1[c], bbv = sb1[c + 1];
            r1[nt * 4 + 0] = lrelu(acc[nt * 4 + 0] + bb0);
            r1[nt * 4 + 1] = lrelu(acc[nt * 4 + 1] + bbv);
            r1[nt * 4 + 2] = lrelu(acc[nt * 4 + 2] + bb0);
            r1[nt * 4 + 3] = lrelu(acc[nt * 4 + 3] + bbv);
        }
    }
    __syncthreads();               // all warps done reading A before rebuild

    // Branch 2
    build_x_tile(sAh, sAl, ego, h0, row0, tid, true);
    __syncthreads();
    run_branch(aH, aL, b2H, b2L, acc);

    // Epilogue
    {
        const int c0 = wn * 64 + (lane & 3) * 2;
        const int rlow  = row0 + wr * 16 + (lane >> 2);
        const int rhigh = rlow + 8;
#pragma unroll
        for (int nt = 0; nt < 8; nt++) {
            const int c = nt * 8 + c0;
            const float bb0 = sb2[c], bbv = sb2[c + 1];
            if (rlow < N_NODES) {
                float2 o;
                o.x = r1[nt * 4 + 0] + lrelu(acc[nt * 4 + 0] + bb0);
                o.y = r1[nt * 4 + 1] + lrelu(acc[nt * 4 + 1] + bbv);
                *reinterpret_cast<float2*>(out + (size_t)rlow * DIM + c) = o;
            }
            if (rhigh < N_NODES) {
                float2 o;
                o.x = r1[nt * 4 + 2] + lrelu(acc[nt * 4 + 2] + bb0);
                o.y = r1[nt * 4 + 3] + lrelu(acc[nt * 4 + 3] + bbv);
                *reinterpret_cast<float2*>(out + (size_t)rhigh * DIM + c) = o;
            }
        }
    }
}

// ---------------------------------------------------------------------------
// Launch
// Inputs: 0=ego 1=h0 2=vals 3=weight 4=w1 5=b1 6=w2 7=b2 8=row 9=col
// ---------------------------------------------------------------------------
extern "C" void kernel_launch(void* const* d_in, const int* in_sizes, int n_in,
                              void* d_out, int out_size) {
    const float* ego    = (const float*)d_in[0];
    const float* h0     = (const float*)d_in[1];
    const float* vals   = (const float*)d_in[2];
    const float* weight = (const float*)d_in[3];
    const float* w1     = (const float*)d_in[4];
    const float* b1     = (const float*)d_in[5];
    const float* w2     = (const float*)d_in[6];
    const float* b2     = (const float*)d_in[7];
    const int*   row    = (const int*)d_in[8];
    const int*   col    = (const int*)d_in[9];
    float* out = (float*)d_out;

    const int E = in_sizes[2];

    // Fold + pack weight matrices
    compute_M_kernel<<<DIM, DIM>>>(weight, w1, w2);

    // ego -> bf16 copy (for the gather)
    {
        const int total = N_NODES * DIM / 8;
        ego_bf16_kernel<<<(total + 255) / 256, 256>>>(ego);
    }

    // CSR build
    zero_cnt_kernel<<<(N_NODES + 255) / 256, 256>>>();
    hist_kernel<<<(E + 255) / 256, 256>>>(row, E);
    scan1_kernel<<<NB_SCAN, SCAN_B>>>();
    scan2_kernel<<<1, 128>>>();
    scan3_kernel<<<(N_NODES + 255) / 256, 256>>>();
    scatter_kernel<<<(E + 255) / 256, 256>>>(row, col, vals, E);

    // Gather SpMM (bf16 gather)
    {
        const int warps_per_block = 8;
        const int blocks = (N_NODES + warps_per_block - 1) / warps_per_block;
        gather_spmm_kernel<<<blocks, warps_per_block * 32>>>();
    }

    // Fused dense via mma.sync
    {
        const int smem_bytes = 6 * TILE_BYTES;   // 208896
        cudaFuncSetAttribute(fused_mma_kernel, cudaFuncAttributeMaxDynamicSharedMemorySize, smem_bytes);
        const int blocks = (N_NODES + 127) / 128;   // 782
        fused_mma_kernel<<<blocks, FM_THREADS, smem_bytes>>>(ego, h0, b1, b2, out);
    }
}